// round 8
// baseline (speedup 1.0000x reference)
#include <cuda_runtime.h>
#include <cuda_bf16.h>

#define BATCH 64
#define NTOK  4096
#define CH    512
#define NUM_KEEP 2458            // ceil(4096 * 0.6)
#define TAIL (NTOK - NUM_KEEP)   // 1638
#define C4   (CH / 4)            // 128 float4 per token row
#define NGROUP 32                // tail groups per batch
#define TAIL_CTAS (BATCH * 8)    // 512 CTAs, 4 groups of 128 lanes each
#define COPY_CTAS 4916           // sel float4s / 4096 per CTA, exact
#define CHUNK 1024               // elements per sorter CTA

typedef unsigned long long u64;

// scratch (device globals; barrier/counter protocol restores them to zero at
// the end of every launch, so graph replays are deterministic)
__device__ u64    g_keys[BATCH * NTOK];      // 2 MB
__device__ int    g_sorted_idx[BATCH * NTOK];
__device__ float  g_tailw[BATCH * TAIL];     // UN-normalized exp weights
__device__ float  g_invsum[BATCH];
__device__ float  g_sum_tmp[BATCH];
__device__ int    g_bar[BATCH * 8];          // 5 per-batch phase barriers
__device__ int    g_done[BATCH];

// ---------------------------------------------------------------------------
// helpers
// ---------------------------------------------------------------------------
__device__ __forceinline__ float decode_score(u64 kk) {
    unsigned u = (unsigned)(kk >> 32);
    return (u & 0x80000000u) ? __uint_as_float(u & 0x7FFFFFFFu)
                             : __uint_as_float(~u);
}

__device__ __forceinline__ void cmpswap(u64& a, u64& c, bool desc) {
    bool sw = desc ? (a < c) : (a > c);
    if (sw) { u64 t = a; a = c; c = t; }
}

// warp finish: levels jstart..2 via shfl (2 elems/thread layout), then j=1.
// d = sort direction for this thread's elements (uniform per thread).
__device__ __forceinline__ void wfin2d(u64& r0, u64& r1,
                                       int base, int jstart, bool d) {
    for (int j = jstart; j >= 2; j >>= 1) {
        int L = j >> 1;
        bool keepmax = (((base & j) == 0) == d);
        u64 o0 = __shfl_xor_sync(0xFFFFFFFFu, r0, L);
        u64 o1 = __shfl_xor_sync(0xFFFFFFFFu, r1, L);
        r0 = keepmax ? (r0 > o0 ? r0 : o0) : (r0 < o0 ? r0 : o0);
        r1 = keepmax ? (r1 > o1 ? r1 : o1) : (r1 < o1 ? r1 : o1);
    }
    cmpswap(r0, r1, d);
}

// per-batch barrier across the 4 sorter CTAs (phase p)
__device__ __forceinline__ void batch_bar(int b, int p) {
    __syncthreads();
    if (threadIdx.x == 0) {
        __threadfence();
        atomicAdd(&g_bar[b * 8 + p], 1);
        while (atomicAdd(&g_bar[b * 8 + p], 0) < 4) __nanosleep(64);
    }
    __syncthreads();
}

// ---------------------------------------------------------------------------
// FUSED SORT: 256 CTAs (4 per batch), 512 threads, 2 elems/thread.
// Phase 1 local chunk sort; phases 2/4 global-memory quad passes for the
// cross-chunk levels; phases 3/5 chunk-local finishes; distributed epilogue.
// ---------------------------------------------------------------------------
__global__ __launch_bounds__(512, 2)
void ts_sort_fused(const float* __restrict__ ax,
                   const float* __restrict__ ay,
                   float* __restrict__ mask_out,
                   float* __restrict__ extra)
{
    __shared__ u64 key[CHUNK];      // 8 KB
    __shared__ float red[16];

    const int cta  = blockIdx.x;      // 0..255
    const int b    = cta >> 2;
    const int c    = cta & 3;
    const bool flip = (c & 1);        // odd chunks ascending
    const int tid  = threadIdx.x;
    const int base = tid << 1;        // local element index (0..1022)
    const int gbase = (c << 10) + base;
    u64* __restrict__ kb = g_keys + b * NTOK;

    // zero this batch's extra slice (4 CTAs x 128 floats)
    if (tid < 128) extra[b * CH + (c << 7) + tid] = 0.0f;

    // ================= phase 1: local chunk sort (k <= 1024) =================
    u64 r0, r1;
    {
        float2 x = *(const float2*)(ax + b * NTOK + gbase);
        float2 y = *(const float2*)(ay + b * NTOK + gbase);
        float s0 = x.x + y.x, s1 = x.y + y.y;
        unsigned u0 = __float_as_uint(s0);
        u0 = (u0 & 0x80000000u) ? ~u0 : (u0 | 0x80000000u);
        unsigned u1 = __float_as_uint(s1);
        u1 = (u1 & 0x80000000u) ? ~u1 : (u1 | 0x80000000u);
        r0 = ((u64)u0 << 32) | (unsigned)(~gbase);
        r1 = ((u64)u1 << 32) | (unsigned)(~(gbase + 1));
    }

    cmpswap(r0, r1, ((base & 2) == 0) != flip);
    for (int k = 4; k <= 64; k <<= 1)
        wfin2d(r0, r1, base, k >> 1, (((base & k) == 0) != flip));

    for (int k = 128; k <= CHUNK; k <<= 1) {
        *(ulonglong2*)&key[base] = make_ulonglong2(r0, r1);
        __syncthreads();
        int j = k >> 1;
        while (j >= 64) {
            int j2 = j >> 1;
            if (tid < 256) {
                int q = tid;
                int i = ((q & ~(j2 - 1)) << 2) | (q & (j2 - 1));
                bool d = (((i & k) == 0) != flip);
                u64 a0 = key[i];
                u64 a1 = key[i + j2];
                u64 a2 = key[i + 2 * j2];
                u64 a3 = key[i + 3 * j2];
                cmpswap(a0, a2, d);
                cmpswap(a1, a3, d);
                cmpswap(a0, a1, d);
                cmpswap(a2, a3, d);
                key[i]          = a0;
                key[i + j2]     = a1;
                key[i + 2 * j2] = a2;
                key[i + 3 * j2] = a3;
            }
            __syncthreads();
            j >>= 2;
        }
        ulonglong2 p = *(ulonglong2*)&key[base];
        r0 = p.x; r1 = p.y;
        wfin2d(r0, r1, base, j, (((base & k) == 0) != flip));
    }
    *(ulonglong2*)(kb + gbase) = make_ulonglong2(r0, r1);

    batch_bar(b, 0);

    // ====== phase 2: k=2048, levels (1024,512) as global quad pass ======
    if (tid < 256) {
        int q = (c << 8) | tid;                    // 0..1023
        int i = ((q & ~511) << 2) | (q & 511);
        bool d = ((i & 2048) == 0);
        u64 a0 = __ldcg(kb + i);
        u64 a1 = __ldcg(kb + i + 512);
        u64 a2 = __ldcg(kb + i + 1024);
        u64 a3 = __ldcg(kb + i + 1536);
        cmpswap(a0, a2, d);
        cmpswap(a1, a3, d);
        cmpswap(a0, a1, d);
        cmpswap(a2, a3, d);
        __stcg(kb + i,        a0);
        __stcg(kb + i + 512,  a1);
        __stcg(kb + i + 1024, a2);
        __stcg(kb + i + 1536, a3);
    }
    batch_bar(b, 1);

    // ====== phase 3: k=2048 local finish (j <= 256) on own chunk ======
    {
        const bool d = (c < 2);     // (i & 2048)==0 for chunks 0,1
        u64* src = kb + (c << 10);
        ulonglong2 p;
        p.x = __ldcg(src + base);
        p.y = __ldcg(src + base + 1);
        key[base] = p.x; key[base + 1] = p.y;
        __syncthreads();
        int j = 256;
        while (j >= 64) {
            int j2 = j >> 1;
            if (tid < 256) {
                int q = tid;
                int i = ((q & ~(j2 - 1)) << 2) | (q & (j2 - 1));
                u64 a0 = key[i];
                u64 a1 = key[i + j2];
                u64 a2 = key[i + 2 * j2];
                u64 a3 = key[i + 3 * j2];
                cmpswap(a0, a2, d);
                cmpswap(a1, a3, d);
                cmpswap(a0, a1, d);
                cmpswap(a2, a3, d);
                key[i]          = a0;
                key[i + j2]     = a1;
                key[i + 2 * j2] = a2;
                key[i + 3 * j2] = a3;
            }
            __syncthreads();
            j >>= 2;
        }
        r0 = key[base]; r1 = key[base + 1];
        wfin2d(r0, r1, base, j, d);     // j = 16 here
        __stcg(src + base,     r0);
        __stcg(src + base + 1, r1);
    }
    batch_bar(b, 2);

    // ====== phase 4: k=4096, levels (2048,1024) as global quad pass ======
    if (tid < 256) {
        int i = (c << 8) | tid;                    // 0..1023
        u64 a0 = __ldcg(kb + i);
        u64 a1 = __ldcg(kb + i + 1024);
        u64 a2 = __ldcg(kb + i + 2048);
        u64 a3 = __ldcg(kb + i + 3072);
        cmpswap(a0, a2, true);
        cmpswap(a1, a3, true);
        cmpswap(a0, a1, true);
        cmpswap(a2, a3, true);
        __stcg(kb + i,        a0);
        __stcg(kb + i + 1024, a1);
        __stcg(kb + i + 2048, a2);
        __stcg(kb + i + 3072, a3);
    }
    batch_bar(b, 3);

    // ====== phase 5: k=4096 local finish (j <= 512, desc) + epilogue ======
    {
        u64* src = kb + (c << 10);
        key[base]     = __ldcg(src + base);
        key[base + 1] = __ldcg(src + base + 1);
        __syncthreads();
        int j = 512;
        while (j >= 64) {
            int j2 = j >> 1;
            if (tid < 256) {
                int q = tid;
                int i = ((q & ~(j2 - 1)) << 2) | (q & (j2 - 1));
                u64 a0 = key[i];
                u64 a1 = key[i + j2];
                u64 a2 = key[i + 2 * j2];
                u64 a3 = key[i + 3 * j2];
                cmpswap(a0, a2, true);
                cmpswap(a1, a3, true);
                cmpswap(a0, a1, true);
                cmpswap(a2, a3, true);
                key[i]          = a0;
                key[i + j2]     = a1;
                key[i + 2 * j2] = a2;
                key[i + 3 * j2] = a3;
            }
            __syncthreads();
            j >>= 2;
        }
        r0 = key[base]; r1 = key[base + 1];
        wfin2d(r0, r1, base, j, true);   // j = 32 here
    }

    // epilogue: ranks gbase, gbase+1 (array index == global rank, descending)
    {
        float lsum = 0.0f;
        int rank0 = gbase;
        int idx0 = (int)(~(unsigned)r0);
        int idx1 = (int)(~(unsigned)r1);
        mask_out[b * NTOK + idx0] = (rank0     < NUM_KEEP) ? 1.0f : 0.0f;
        mask_out[b * NTOK + idx1] = (rank0 + 1 < NUM_KEEP) ? 1.0f : 0.0f;
        if (rank0 >= NUM_KEEP) {           // unnormalized softmax (no max-sub:
            float e = expf(decode_score(r0));   // tail scores are small, fp32-safe)
            g_tailw[b * TAIL + (rank0 - NUM_KEEP)] = e;
            lsum += e;
        }
        if (rank0 + 1 >= NUM_KEEP) {
            float e = expf(decode_score(r1));
            g_tailw[b * TAIL + (rank0 + 1 - NUM_KEEP)] = e;
            lsum += e;
        }
        *(int2*)(g_sorted_idx + b * NTOK + gbase) = make_int2(idx0, idx1);

        for (int off = 16; off > 0; off >>= 1)
            lsum += __shfl_down_sync(0xFFFFFFFFu, lsum, off);
        if ((tid & 31) == 0) red[tid >> 5] = lsum;
        __syncthreads();
        if (tid < 32) {
            float v = (tid < 16) ? red[tid] : 0.0f;
            for (int off = 8; off > 0; off >>= 1)
                v += __shfl_down_sync(0xFFFFFFFFu, v, off);
            if (tid == 0 && v != 0.0f) atomicAdd(&g_sum_tmp[b], v);
        }
    }
    batch_bar(b, 4);

    if (tid == 0) {
        if (c == 0) {
            float s = __ldcg(&g_sum_tmp[b]);
            g_invsum[b] = 1.0f / s;
        }
        int old = atomicAdd(&g_done[b], 1);
        if (old == 3) {                 // last CTA resets all batch-b state
            #pragma unroll
            for (int p = 0; p < 5; ++p) atomicExch(&g_bar[b * 8 + p], 0);
            atomicExch(&g_sum_tmp[b], 0.0f);
            atomicExch(&g_done[b], 0);
        }
    }
}

// ---------------------------------------------------------------------------
// MAIN kernel: tail accumulation + gather copy (unchanged, at HBM roofline)
// ---------------------------------------------------------------------------
__global__ __launch_bounds__(512)
void ts_main_kernel(const float* __restrict__ tokens,
                    float* __restrict__ sel,
                    float* __restrict__ extra)
{
    if (blockIdx.x < TAIL_CTAS) {
        const int b    = blockIdx.x >> 3;
        const int g    = ((blockIdx.x & 7) << 2) | (threadIdx.x >> 7); // 0..31
        const int lane = threadIdx.x & 127;

        const int* __restrict__ sidx = g_sorted_idx + b * NTOK + NUM_KEEP;
        const float* __restrict__ w  = g_tailw + b * TAIL;
        const float4* __restrict__ tok4 = (const float4*)tokens
                                          + ((long long)b * NTOK << 7);

        float4 acc = make_float4(0.f, 0.f, 0.f, 0.f);
        int r = g;
        for (; r + NGROUP < TAIL; r += 2 * NGROUP) {
            int   i0 = sidx[r],    i1 = sidx[r + NGROUP];
            float w0 = w[r],       w1 = w[r + NGROUP];
            float4 v0 = __ldcs(&tok4[((long long)i0 << 7) + lane]);
            float4 v1 = __ldcs(&tok4[((long long)i1 << 7) + lane]);
            acc.x += w0 * v0.x + w1 * v1.x;
            acc.y += w0 * v0.y + w1 * v1.y;
            acc.z += w0 * v0.z + w1 * v1.z;
            acc.w += w0 * v0.w + w1 * v1.w;
        }
        if (r < TAIL) {
            int i0 = sidx[r];
            float w0 = w[r];
            float4 v0 = __ldcs(&tok4[((long long)i0 << 7) + lane]);
            acc.x += w0 * v0.x; acc.y += w0 * v0.y;
            acc.z += w0 * v0.z; acc.w += w0 * v0.w;
        }
        float s = g_invsum[b];
        float* dst = extra + b * CH + (lane << 2);
        atomicAdd(dst + 0, acc.x * s);
        atomicAdd(dst + 1, acc.y * s);
        atomicAdd(dst + 2, acc.z * s);
        atomicAdd(dst + 3, acc.w * s);
    } else {
        const int cta = blockIdx.x - TAIL_CTAS;
        const int v0  = (cta << 12) + threadIdx.x;

        long long srcoff[8];
        #pragma unroll
        for (int i = 0; i < 8; ++i) {
            int v = v0 + (i << 9);
            int row  = v >> 7;                 // b*NUM_KEEP + r
            int lane = v & 127;
            int b = row / NUM_KEEP;
            int r = row - b * NUM_KEEP;
            int idx = __ldg(&g_sorted_idx[b * NTOK + r]);
            srcoff[i] = (((long long)b * NTOK + idx) << 7) + lane;
        }
        float4 val[8];
        #pragma unroll
        for (int i = 0; i < 8; ++i)
            val[i] = __ldcs(((const float4*)tokens) + srcoff[i]);
        #pragma unroll
        for (int i = 0; i < 8; ++i)
            __stcs(((float4*)sel) + v0 + (i << 9), val[i]);
    }
}

// ---------------------------------------------------------------------------
extern "C" void kernel_launch(void* const* d_in, const int* in_sizes, int n_in,
                              void* d_out, int out_size)
{
    const float* tokens = (const float*)d_in[0];
    const float* ax     = (const float*)d_in[1];
    const float* ay     = (const float*)d_in[2];

    float* out = (float*)d_out;
    float* sel   = out;                                      // B*NUM_KEEP*C
    float* extra = out + (long long)BATCH * NUM_KEEP * CH;   // B*C
    float* mask  = extra + (long long)BATCH * CH;            // B*N

    ts_sort_fused<<<BATCH * 4, 512>>>(ax, ay, mask, extra);
    ts_main_kernel<<<TAIL_CTAS + COPY_CTAS, 512>>>(tokens, sel, extra);
}

// round 10
// speedup vs baseline: 1.0289x; 1.0289x over previous
#include <cuda_runtime.h>
#include <cuda_bf16.h>

#define BATCH 64
#define NTOK  4096
#define CH    512
#define NUM_KEEP 2458            // ceil(4096 * 0.6)
#define TAIL (NTOK - NUM_KEEP)   // 1638
#define C4   (CH / 4)            // 128 float4 per token row
#define NGROUP 32                // tail groups per batch
#define TAIL_CTAS (BATCH * 8)    // 512 CTAs, 4 groups of 128 lanes each
#define COPY_CTAS 4916           // sel float4s / 4096 per CTA, exact
#define CHUNK 1024               // elements per sorter CTA

typedef unsigned long long u64;

// scratch (device globals; g_sum_tmp is re-zeroed by kernel A every launch,
// everything else is fully overwritten -> graph replays are deterministic)
__device__ u64    g_keys[BATCH * NTOK];      // 2 MB, chunk-sorted descending
__device__ int    g_sorted_idx[BATCH * NTOK];
__device__ float  g_tailw[BATCH * TAIL];     // UN-normalized exp weights
__device__ float  g_sum_tmp[BATCH];          // tail softmax denominator

// ---------------------------------------------------------------------------
// helpers
// ---------------------------------------------------------------------------
__device__ __forceinline__ float decode_score(u64 kk) {
    unsigned u = (unsigned)(kk >> 32);
    return (u & 0x80000000u) ? __uint_as_float(u & 0x7FFFFFFFu)
                             : __uint_as_float(~u);
}

__device__ __forceinline__ void cmpswap(u64& a, u64& c, bool desc) {
    bool sw = desc ? (a < c) : (a > c);
    if (sw) { u64 t = a; a = c; c = t; }
}

// warp finish: levels jstart..2 via shfl (2 elems/thread layout), then j=1.
__device__ __forceinline__ void wfin2d(u64& r0, u64& r1,
                                       int base, int jstart, bool d) {
    for (int j = jstart; j >= 2; j >>= 1) {
        int L = j >> 1;
        bool keepmax = (((base & j) == 0) == d);
        u64 o0 = __shfl_xor_sync(0xFFFFFFFFu, r0, L);
        u64 o1 = __shfl_xor_sync(0xFFFFFFFFu, r1, L);
        r0 = keepmax ? (r0 > o0 ? r0 : o0) : (r0 < o0 ? r0 : o0);
        r1 = keepmax ? (r1 > o1 ? r1 : o1) : (r1 < o1 ? r1 : o1);
    }
    cmpswap(r0, r1, d);
}

// ---------------------------------------------------------------------------
// Kernel A: 4 CTAs/batch, 512 threads, 2 elems/thread: sort each 1024-chunk
// DESCENDING. Also zeroes the extra slice and the per-batch softmax sum.
// ---------------------------------------------------------------------------
__global__ __launch_bounds__(512)
void ts_sort1_kernel(const float* __restrict__ ax,
                     const float* __restrict__ ay,
                     float* __restrict__ extra)
{
    __shared__ u64 key[CHUNK];   // 8 KB

    const int chunk = blockIdx.x;        // 0..255
    const int b     = chunk >> 2;
    const int c     = chunk & 3;
    const int tid   = threadIdx.x;
    const int base  = tid << 1;          // element e0 in chunk
    const int gbase = (c << 10) + base;  // token index within batch

    if (tid < 128) extra[b * CH + (c << 7) + tid] = 0.0f;
    if (tid == 0 && c == 0) g_sum_tmp[b] = 0.0f;

    u64 r0, r1;
    {
        float2 x = *(const float2*)(ax + b * NTOK + gbase);
        float2 y = *(const float2*)(ay + b * NTOK + gbase);
        float s0 = x.x + y.x, s1 = x.y + y.y;
        unsigned u0 = __float_as_uint(s0);
        u0 = (u0 & 0x80000000u) ? ~u0 : (u0 | 0x80000000u);
        unsigned u1 = __float_as_uint(s1);
        u1 = (u1 & 0x80000000u) ? ~u1 : (u1 | 0x80000000u);
        r0 = ((u64)u0 << 32) | (unsigned)(~gbase);
        r1 = ((u64)u1 << 32) | (unsigned)(~(gbase + 1));
    }

    // k = 2..64 : registers + shuffles only (descending network)
    cmpswap(r0, r1, (base & 2) == 0);
    for (int k = 4; k <= 64; k <<= 1)
        wfin2d(r0, r1, base, k >> 1, ((base & k) == 0));

    // k = 128..1024 : smem quad passes (levels j,j/2 together), warp finish
    for (int k = 128; k <= CHUNK; k <<= 1) {
        *(ulonglong2*)&key[base] = make_ulonglong2(r0, r1);
        __syncthreads();
        int j = k >> 1;
        while (j >= 64) {
            int j2 = j >> 1;
            if (tid < 256) {
                int q = tid;
                int i = ((q & ~(j2 - 1)) << 2) | (q & (j2 - 1));
                bool d = ((i & k) == 0);
                u64 a0 = key[i];
                u64 a1 = key[i + j2];
                u64 a2 = key[i + 2 * j2];
                u64 a3 = key[i + 3 * j2];
                cmpswap(a0, a2, d);
                cmpswap(a1, a3, d);
                cmpswap(a0, a1, d);
                cmpswap(a2, a3, d);
                key[i]          = a0;
                key[i + j2]     = a1;
                key[i + 2 * j2] = a2;
                key[i + 3 * j2] = a3;
            }
            __syncthreads();
            j >>= 2;
        }
        ulonglong2 p = *(ulonglong2*)&key[base];
        r0 = p.x; r1 = p.y;
        wfin2d(r0, r1, base, j, ((base & k) == 0));   // j is 32 or 16 here
    }

    *(ulonglong2*)(g_keys + b * NTOK + gbase) = make_ulonglong2(r0, r1);
}

// ---------------------------------------------------------------------------
// Kernel B: merge-by-rank. 4 CTAs per batch; each loads all 4 chunks into
// smem and computes global rank = own-chunk position + count_greater in the
// other 3 chunks. Binary search needs 11 guarded steps: lo in [0,1024] has
// 1025 candidates (10 steps leave 2 -> the R9 off-by-one bug).
// ---------------------------------------------------------------------------
__global__ __launch_bounds__(512)
void ts_merge_kernel(float* __restrict__ mask_out)
{
    __shared__ u64 D[NTOK];      // 32 KB
    __shared__ float red[16];

    const int cta = blockIdx.x;          // 0..255
    const int b   = cta >> 2;
    const int c   = cta & 3;
    const int tid = threadIdx.x;

    // load the whole batch's keys (vectorized, 4 iters of ulonglong2)
    {
        const ulonglong2* src = (const ulonglong2*)(g_keys + b * NTOK);
        ulonglong2* dst = (ulonglong2*)D;
        #pragma unroll
        for (int i = 0; i < 4; ++i)
            dst[tid + (i << 9)] = src[tid + (i << 9)];
    }
    __syncthreads();

    float lsum = 0.0f;

    #pragma unroll
    for (int m = 0; m < 2; ++m) {
        const int pos = (tid << 1) + m;          // position in own chunk
        const u64 e = D[(c << 10) + pos];

        int rank = pos;
        #pragma unroll
        for (int oc = 0; oc < 4; ++oc) {
            if (oc == c) continue;
            const u64* __restrict__ A = D + (oc << 10);
            int lo = 0, hi = CHUNK;
            #pragma unroll
            for (int it = 0; it < 11; ++it) {    // 11 steps for 1025 outcomes
                if (lo < hi) {
                    int mid = (lo + hi) >> 1;
                    if (A[mid] > e) lo = mid + 1; else hi = mid;
                }
            }
            rank += lo;                          // # elements > e in A
        }

        const int idx = (int)(~(unsigned)e);
        g_sorted_idx[b * NTOK + rank] = idx;
        mask_out[b * NTOK + idx] = (rank < NUM_KEEP) ? 1.0f : 0.0f;
        if (rank >= NUM_KEEP) {
            // unnormalized softmax (scores are O(1); exp is fp32-safe —
            // scheme validated in R8 at rel_err 2e-7)
            float w = expf(decode_score(e));
            g_tailw[b * TAIL + (rank - NUM_KEEP)] = w;
            lsum += w;
        }
    }

    // block-reduce lsum, one atomicAdd per CTA into the batch denominator
    for (int off = 16; off > 0; off >>= 1)
        lsum += __shfl_down_sync(0xFFFFFFFFu, lsum, off);
    if ((tid & 31) == 0) red[tid >> 5] = lsum;
    __syncthreads();
    if (tid < 16) {
        float v = red[tid];
        for (int off = 8; off > 0; off >>= 1)
            v += __shfl_down_sync(0x0000FFFFu, v, off);
        if (tid == 0) atomicAdd(&g_sum_tmp[b], v);
    }
}

// ---------------------------------------------------------------------------
// MAIN kernel: tail accumulation + gather copy (unchanged, at HBM roofline;
// tail path derives 1/sum from g_sum_tmp directly)
// ---------------------------------------------------------------------------
__global__ __launch_bounds__(512)
void ts_main_kernel(const float* __restrict__ tokens,
                    float* __restrict__ sel,
                    float* __restrict__ extra)
{
    if (blockIdx.x < TAIL_CTAS) {
        const int b    = blockIdx.x >> 3;
        const int g    = ((blockIdx.x & 7) << 2) | (threadIdx.x >> 7); // 0..31
        const int lane = threadIdx.x & 127;

        const int* __restrict__ sidx = g_sorted_idx + b * NTOK + NUM_KEEP;
        const float* __restrict__ w  = g_tailw + b * TAIL;
        const float4* __restrict__ tok4 = (const float4*)tokens
                                          + ((long long)b * NTOK << 7);

        float4 acc = make_float4(0.f, 0.f, 0.f, 0.f);
        int r = g;
        for (; r + NGROUP < TAIL; r += 2 * NGROUP) {
            int   i0 = sidx[r],    i1 = sidx[r + NGROUP];
            float w0 = w[r],       w1 = w[r + NGROUP];
            float4 v0 = __ldcs(&tok4[((long long)i0 << 7) + lane]);
            float4 v1 = __ldcs(&tok4[((long long)i1 << 7) + lane]);
            acc.x += w0 * v0.x + w1 * v1.x;
            acc.y += w0 * v0.y + w1 * v1.y;
            acc.z += w0 * v0.z + w1 * v1.z;
            acc.w += w0 * v0.w + w1 * v1.w;
        }
        if (r < TAIL) {
            int i0 = sidx[r];
            float w0 = w[r];
            float4 v0 = __ldcs(&tok4[((long long)i0 << 7) + lane]);
            acc.x += w0 * v0.x; acc.y += w0 * v0.y;
            acc.z += w0 * v0.z; acc.w += w0 * v0.w;
        }
        float s = 1.0f / g_sum_tmp[b];
        float* dst = extra + b * CH + (lane << 2);
        atomicAdd(dst + 0, acc.x * s);
        atomicAdd(dst + 1, acc.y * s);
        atomicAdd(dst + 2, acc.z * s);
        atomicAdd(dst + 3, acc.w * s);
    } else {
        const int cta = blockIdx.x - TAIL_CTAS;
        const int v0  = (cta << 12) + threadIdx.x;

        long long srcoff[8];
        #pragma unroll
        for (int i = 0; i < 8; ++i) {
            int v = v0 + (i << 9);
            int row  = v >> 7;                 // b*NUM_KEEP + r
            int lane = v & 127;
            int b = row / NUM_KEEP;
            int r = row - b * NUM_KEEP;
            int idx = __ldg(&g_sorted_idx[b * NTOK + r]);
            srcoff[i] = (((long long)b * NTOK + idx) << 7) + lane;
        }
        float4 val[8];
        #pragma unroll
        for (int i = 0; i < 8; ++i)
            val[i] = __ldcs(((const float4*)tokens) + srcoff[i]);
        #pragma unroll
        for (int i = 0; i < 8; ++i)
            __stcs(((float4*)sel) + v0 + (i << 9), val[i]);
    }
}

// ---------------------------------------------------------------------------
extern "C" void kernel_launch(void* const* d_in, const int* in_sizes, int n_in,
                              void* d_out, int out_size)
{
    const float* tokens = (const float*)d_in[0];
    const float* ax     = (const float*)d_in[1];
    const float* ay     = (const float*)d_in[2];

    float* out = (float*)d_out;
    float* sel   = out;                                      // B*NUM_KEEP*C
    float* extra = out + (long long)BATCH * NUM_KEEP * CH;   // B*C
    float* mask  = extra + (long long)BATCH * CH;            // B*N

    ts_sort1_kernel<<<BATCH * 4, 512>>>(ax, ay, extra);
    ts_merge_kernel<<<BATCH * 4, 512>>>(mask);
    ts_main_kernel<<<TAIL_CTAS + COPY_CTAS, 512>>>(tokens, sel, extra);
}